// round 1
// baseline (speedup 1.0000x reference)
#include <cuda_runtime.h>
#include <math.h>

#define NN 100000
#define NE 3200000
#define F_IN 256
#define HID 16
#define NC 32

// scratch (device globals; no allocation allowed)
__device__ float g_xs[NN * 48];    // [xs0 | xs1 | xroot]
__device__ float g_agg1[NN * 16];
__device__ int   g_cnt[NN];
__device__ float g_inv[NN];
__device__ float g_h[NN * 16];
__device__ float g_a01[NN * 32];   // [sum (1-u) h | sum u h]

// ---------------------------------------------------------------------------
// zero accumulators
__global__ __launch_bounds__(256) void zero_kernel() {
    int i = blockIdx.x * 256 + threadIdx.x;
    if (i < NN * 32) g_a01[i] = 0.f;
    if (i < NN * 16) g_agg1[i] = 0.f;
    if (i < NN) g_cnt[i] = 0;
}

// ---------------------------------------------------------------------------
// GEMM1: xs[n, 0:48] = x[n,:] @ [W1_0 | W1_1 | root1]
// block: 256 threads, 128 nodes; K staged in chunks of 64.
// thread: 4 nodes x 6 cols = 24 accumulators.
__global__ __launch_bounds__(256) void gemm1_kernel(
    const float* __restrict__ x, const float* __restrict__ W1,
    const float* __restrict__ root1) {
    __shared__ float xt[64][132];   // [k][node], padded
    __shared__ float wc[64][48];    // [k][col]

    const int tid = threadIdx.x;
    const int cg  = tid & 7;        // col group -> cols cg*6 .. cg*6+5
    const int ng  = tid >> 3;       // node group -> nodes 4*ng .. 4*ng+3
    const int n0  = blockIdx.x * 128;

    float acc[24];
#pragma unroll
    for (int i = 0; i < 24; i++) acc[i] = 0.f;

    for (int k0 = 0; k0 < F_IN; k0 += 64) {
        // stage x: 128 nodes x 64 k, transposed into xt[k][node]
        {
            int nl = tid >> 1;              // local node 0..127
            int n  = n0 + nl;
            int half = tid & 1;
#pragma unroll
            for (int i = 0; i < 8; i++) {
                int q = half * 8 + i;       // float4 index within 64 k
                float4 v = make_float4(0.f, 0.f, 0.f, 0.f);
                if (n < NN)
                    v = *(const float4*)(x + (size_t)n * F_IN + k0 + q * 4);
                xt[q * 4 + 0][nl] = v.x;
                xt[q * 4 + 1][nl] = v.y;
                xt[q * 4 + 2][nl] = v.z;
                xt[q * 4 + 3][nl] = v.w;
            }
        }
        // stage combined weights: wc[kk][c]
        for (int i = tid; i < 64 * 48; i += 256) {
            int kk = i / 48, c = i % 48;
            int f = k0 + kk;
            float w;
            if (c < 32) w = W1[(c >> 4) * (F_IN * HID) + f * HID + (c & 15)];
            else        w = root1[f * HID + (c - 32)];
            wc[kk][c] = w;
        }
        __syncthreads();

#pragma unroll 4
        for (int kk = 0; kk < 64; kk++) {
            float2 xa = *(const float2*)&xt[kk][ng * 4];
            float2 xb = *(const float2*)&xt[kk][ng * 4 + 2];
#pragma unroll
            for (int j = 0; j < 6; j++) {
                float w = wc[kk][cg * 6 + j];
                acc[j]      += xa.x * w;
                acc[6 + j]  += xa.y * w;
                acc[12 + j] += xb.x * w;
                acc[18 + j] += xb.y * w;
            }
        }
        __syncthreads();
    }

#pragma unroll
    for (int v = 0; v < 4; v++) {
        int n = n0 + ng * 4 + v;
        if (n < NN) {
#pragma unroll
            for (int j = 0; j < 6; j++)
                g_xs[(size_t)n * 48 + cg * 6 + j] = acc[v * 6 + j];
        }
    }
}

// ---------------------------------------------------------------------------
// Edge pass 1: agg1[dst] += (1-u)*xs0[src] + u*xs1[src]; cnt[dst]++
__global__ __launch_bounds__(256) void edge1_kernel(
    const int* __restrict__ ei, const float* __restrict__ ea) {
    int e = blockIdx.x * 256 + threadIdx.x;
    if (e >= NE) return;
    int s = ei[e];
    int d = ei[NE + e];
    float u = fminf(fmaxf(ea[e], 0.f), 1.f);
    float w0 = 1.f - u;

    const float4* p = (const float4*)(g_xs + (size_t)s * 48);
    float4 a0 = p[0], a1 = p[1], a2 = p[2], a3 = p[3];  // xs0
    float4 b0 = p[4], b1 = p[5], b2 = p[6], b3 = p[7];  // xs1
    float* q = g_agg1 + (size_t)d * 16;

    atomicAdd(q + 0,  w0 * a0.x + u * b0.x);
    atomicAdd(q + 1,  w0 * a0.y + u * b0.y);
    atomicAdd(q + 2,  w0 * a0.z + u * b0.z);
    atomicAdd(q + 3,  w0 * a0.w + u * b0.w);
    atomicAdd(q + 4,  w0 * a1.x + u * b1.x);
    atomicAdd(q + 5,  w0 * a1.y + u * b1.y);
    atomicAdd(q + 6,  w0 * a1.z + u * b1.z);
    atomicAdd(q + 7,  w0 * a1.w + u * b1.w);
    atomicAdd(q + 8,  w0 * a2.x + u * b2.x);
    atomicAdd(q + 9,  w0 * a2.y + u * b2.y);
    atomicAdd(q + 10, w0 * a2.z + u * b2.z);
    atomicAdd(q + 11, w0 * a2.w + u * b2.w);
    atomicAdd(q + 12, w0 * a3.x + u * b3.x);
    atomicAdd(q + 13, w0 * a3.y + u * b3.y);
    atomicAdd(q + 14, w0 * a3.z + u * b3.z);
    atomicAdd(q + 15, w0 * a3.w + u * b3.w);
    atomicAdd(&g_cnt[d], 1);
}

// ---------------------------------------------------------------------------
// Node pass 1: h = elu(agg1/cnt + xroot + bias1); store inv_cnt
__global__ __launch_bounds__(256) void node1_kernel(const float* __restrict__ bias1) {
    int idx = blockIdx.x * 256 + threadIdx.x;
    if (idx >= NN * 16) return;
    int n = idx >> 4, j = idx & 15;
    float inv = 1.f / fmaxf((float)g_cnt[n], 1.f);
    if (j == 0) g_inv[n] = inv;
    float v = g_agg1[idx] * inv + g_xs[(size_t)n * 48 + 32 + j] + bias1[j];
    g_h[idx] = v > 0.f ? v : expm1f(v);
}

// ---------------------------------------------------------------------------
// Edge pass 2: a01[dst][0:16] += (1-u)*h[src]; a01[dst][16:32] += u*h[src]
__global__ __launch_bounds__(256) void edge2_kernel(
    const int* __restrict__ ei, const float* __restrict__ ea) {
    int e = blockIdx.x * 256 + threadIdx.x;
    if (e >= NE) return;
    int s = ei[e];
    int d = ei[NE + e];
    float u = fminf(fmaxf(ea[e], 0.f), 1.f);
    float w0 = 1.f - u;

    const float4* p = (const float4*)(g_h + (size_t)s * 16);
    float4 h0 = p[0], h1 = p[1], h2 = p[2], h3 = p[3];
    float* q = g_a01 + (size_t)d * 32;

    atomicAdd(q + 0,  w0 * h0.x);
    atomicAdd(q + 1,  w0 * h0.y);
    atomicAdd(q + 2,  w0 * h0.z);
    atomicAdd(q + 3,  w0 * h0.w);
    atomicAdd(q + 4,  w0 * h1.x);
    atomicAdd(q + 5,  w0 * h1.y);
    atomicAdd(q + 6,  w0 * h1.z);
    atomicAdd(q + 7,  w0 * h1.w);
    atomicAdd(q + 8,  w0 * h2.x);
    atomicAdd(q + 9,  w0 * h2.y);
    atomicAdd(q + 10, w0 * h2.z);
    atomicAdd(q + 11, w0 * h2.w);
    atomicAdd(q + 12, w0 * h3.x);
    atomicAdd(q + 13, w0 * h3.y);
    atomicAdd(q + 14, w0 * h3.z);
    atomicAdd(q + 15, w0 * h3.w);
    atomicAdd(q + 16, u * h0.x);
    atomicAdd(q + 17, u * h0.y);
    atomicAdd(q + 18, u * h0.z);
    atomicAdd(q + 19, u * h0.w);
    atomicAdd(q + 20, u * h1.x);
    atomicAdd(q + 21, u * h1.y);
    atomicAdd(q + 22, u * h1.z);
    atomicAdd(q + 23, u * h1.w);
    atomicAdd(q + 24, u * h2.x);
    atomicAdd(q + 25, u * h2.y);
    atomicAdd(q + 26, u * h2.z);
    atomicAdd(q + 27, u * h2.w);
    atomicAdd(q + 28, u * h3.x);
    atomicAdd(q + 29, u * h3.y);
    atomicAdd(q + 30, u * h3.z);
    atomicAdd(q + 31, u * h3.w);
}

// ---------------------------------------------------------------------------
// Final: out = log_softmax( inv*(a01 @ [W2_0;W2_1]) + h @ root2 + bias2 )
// warp per node, 8 nodes per block; per-lane weight registers.
__global__ __launch_bounds__(256) void final_kernel(
    const float* __restrict__ W2, const float* __restrict__ root2,
    const float* __restrict__ bias2, float* __restrict__ out) {
    __shared__ float a_sm[8][48];   // [node][ a01(32) | h(16) ]
    const int lane = threadIdx.x & 31;
    const int wrp  = threadIdx.x >> 5;
    const int nb   = blockIdx.x * 8;

    // per-lane weight columns
    float wv[48];
#pragma unroll
    for (int k = 0; k < 16; k++) wv[k]      = W2[k * NC + lane];              // W2_0[k][lane]
#pragma unroll
    for (int k = 0; k < 16; k++) wv[16 + k] = W2[16 * NC + k * NC + lane];    // W2_1[k][lane]
#pragma unroll
    for (int k = 0; k < 16; k++) wv[32 + k] = root2[k * NC + lane];
    float bias = bias2[lane];

    {
        int t = threadIdx.x;
        int nd = t >> 5, c = t & 31;
        int n = nb + nd;
        a_sm[nd][c] = (n < NN) ? g_a01[(size_t)n * 32 + c] : 0.f;
        if (c < 16)
            a_sm[nd][32 + c] = (n < NN) ? g_h[(size_t)n * 16 + c] : 0.f;
    }
    __syncthreads();

    int n = nb + wrp;
    if (n >= NN) return;

    float s1 = 0.f, s2 = 0.f;
#pragma unroll
    for (int k = 0; k < 32; k++) s1 += a_sm[wrp][k] * wv[k];
#pragma unroll
    for (int k = 0; k < 16; k++) s2 += a_sm[wrp][32 + k] * wv[32 + k];
    float o = s1 * g_inv[n] + s2 + bias;

    // log_softmax across warp (32 classes == 32 lanes)
    float m = o;
#pragma unroll
    for (int off = 16; off; off >>= 1)
        m = fmaxf(m, __shfl_xor_sync(0xffffffffu, m, off));
    float ex = __expf(o - m);
    float ssum = ex;
#pragma unroll
    for (int off = 16; off; off >>= 1)
        ssum += __shfl_xor_sync(0xffffffffu, ssum, off);
    out[(size_t)n * 32 + lane] = o - m - logf(ssum);
}

// ---------------------------------------------------------------------------
extern "C" void kernel_launch(void* const* d_in, const int* in_sizes, int n_in,
                              void* d_out, int out_size) {
    const float* x     = (const float*)d_in[0];
    const float* ea    = (const float*)d_in[1];
    const float* W1    = (const float*)d_in[2];
    const float* root1 = (const float*)d_in[3];
    const float* bias1 = (const float*)d_in[4];
    const float* W2    = (const float*)d_in[5];
    const float* root2 = (const float*)d_in[6];
    const float* bias2 = (const float*)d_in[7];
    const int*   ei    = (const int*)d_in[8];
    float* out = (float*)d_out;

    zero_kernel<<<(NN * 32 + 255) / 256, 256>>>();
    gemm1_kernel<<<(NN + 127) / 128, 256>>>(x, W1, root1);
    edge1_kernel<<<(NE + 255) / 256, 256>>>(ei, ea);
    node1_kernel<<<(NN * 16 + 255) / 256, 256>>>(bias1);
    edge2_kernel<<<(NE + 255) / 256, 256>>>(ei, ea);
    final_kernel<<<(NN + 7) / 8, 256>>>(W2, root2, bias2, out);
}

// round 2
// speedup vs baseline: 2.3537x; 2.3537x over previous
#include <cuda_runtime.h>
#include <math.h>

#define NN 100000
#define NE 3200000
#define F_IN 256
#define HID 16
#define NC 32
#define NSCB 98          // ceil(NN/1024) scan blocks

// scratch (device globals; allocation is forbidden)
__device__ float  g_xs01[NN * 32];   // [xs0(16) | xs1(16)] interleaved per node
__device__ float  g_xroot[NN * 16];
__device__ float  g_h[NN * 16];
__device__ int    g_cnt[NN];
__device__ int    g_off[NN];
__device__ int    g_cur[NN];
__device__ float  g_inv[NN];
__device__ float2 g_edges[NE];       // {src as float bits, u}
__device__ int    g_bsum[NSCB];
__device__ int    g_boff[NSCB];

// ---------------------------------------------------------------------------
__global__ __launch_bounds__(256) void zero_kernel() {
    int i = blockIdx.x * 256 + threadIdx.x;
    if (i < NN) g_cnt[i] = 0;
}

// ---------------------------------------------------------------------------
// histogram of dst
__global__ __launch_bounds__(256) void hist_kernel(const int* __restrict__ ei) {
    int e = blockIdx.x * 256 + threadIdx.x;
    if (e >= NE) return;
    atomicAdd(&g_cnt[ei[NE + e]], 1);
}

// block sums (1024 elems per block)
__global__ __launch_bounds__(256) void scanA_kernel() {
    __shared__ int sh[256];
    int b = blockIdx.x, t = threadIdx.x;
    int base = b * 1024 + t * 4;
    int s = 0;
#pragma unroll
    for (int j = 0; j < 4; j++)
        if (base + j < NN) s += g_cnt[base + j];
    sh[t] = s;
    __syncthreads();
    for (int o = 128; o; o >>= 1) {
        if (t < o) sh[t] += sh[t + o];
        __syncthreads();
    }
    if (t == 0) g_bsum[b] = sh[0];
}

// exclusive scan of block sums (tiny)
__global__ void scanB_kernel() {
    if (threadIdx.x == 0) {
        int s = 0;
        for (int i = 0; i < NSCB; i++) { int v = g_bsum[i]; g_boff[i] = s; s += v; }
    }
}

// final offsets + inv-degree
__global__ __launch_bounds__(256) void scanC_kernel() {
    int b = blockIdx.x, t = threadIdx.x;
    int base = b * 1024 + t * 4;
    int v[4], pre[4];
    int s = 0;
#pragma unroll
    for (int j = 0; j < 4; j++) {
        v[j] = (base + j < NN) ? g_cnt[base + j] : 0;
        pre[j] = s; s += v[j];
    }
    int lane = t & 31, w = t >> 5;
    int x = s;
#pragma unroll
    for (int o = 1; o < 32; o <<= 1) {
        int y = __shfl_up_sync(0xffffffffu, x, o);
        if (lane >= o) x += y;
    }
    __shared__ int wsum[8];
    if (lane == 31) wsum[w] = x;
    __syncthreads();
    if (t == 0) {
        int a = 0;
        for (int i = 0; i < 8; i++) { int tmp = wsum[i]; wsum[i] = a; a += tmp; }
    }
    __syncthreads();
    int excl = x - s + wsum[w] + g_boff[b];
#pragma unroll
    for (int j = 0; j < 4; j++) {
        if (base + j < NN) {
            int o = excl + pre[j];
            g_off[base + j] = o;
            g_cur[base + j] = o;
            g_inv[base + j] = 1.f / fmaxf((float)v[j], 1.f);
        }
    }
}

// scatter edges into CSR segments
__global__ __launch_bounds__(256) void scatter_kernel(
    const int* __restrict__ ei, const float* __restrict__ ea) {
    int e = blockIdx.x * 256 + threadIdx.x;
    if (e >= NE) return;
    int s = ei[e];
    int d = ei[NE + e];
    float u = fminf(fmaxf(ea[e], 0.f), 1.f);
    int slot = atomicAdd(&g_cur[d], 1);
    g_edges[slot] = make_float2(__int_as_float(s), u);
}

// ---------------------------------------------------------------------------
// GEMM1: [xs0|xs1] -> g_xs01, root part -> g_xroot
__global__ __launch_bounds__(256) void gemm1_kernel(
    const float* __restrict__ x, const float* __restrict__ W1,
    const float* __restrict__ root1) {
    __shared__ float xt[64][132];
    __shared__ float wc[64][48];

    const int tid = threadIdx.x;
    const int cg  = tid & 7;
    const int ng  = tid >> 3;
    const int n0  = blockIdx.x * 128;

    float acc[24];
#pragma unroll
    for (int i = 0; i < 24; i++) acc[i] = 0.f;

    for (int k0 = 0; k0 < F_IN; k0 += 64) {
        {
            int nl = tid >> 1;
            int n  = n0 + nl;
            int half = tid & 1;
#pragma unroll
            for (int i = 0; i < 8; i++) {
                int q = half * 8 + i;
                float4 v = make_float4(0.f, 0.f, 0.f, 0.f);
                if (n < NN)
                    v = *(const float4*)(x + (size_t)n * F_IN + k0 + q * 4);
                xt[q * 4 + 0][nl] = v.x;
                xt[q * 4 + 1][nl] = v.y;
                xt[q * 4 + 2][nl] = v.z;
                xt[q * 4 + 3][nl] = v.w;
            }
        }
        for (int i = tid; i < 64 * 48; i += 256) {
            int kk = i / 48, c = i % 48;
            int f = k0 + kk;
            float w;
            if (c < 32) w = W1[(c >> 4) * (F_IN * HID) + f * HID + (c & 15)];
            else        w = root1[f * HID + (c - 32)];
            wc[kk][c] = w;
        }
        __syncthreads();

#pragma unroll 4
        for (int kk = 0; kk < 64; kk++) {
            float2 xa = *(const float2*)&xt[kk][ng * 4];
            float2 xb = *(const float2*)&xt[kk][ng * 4 + 2];
#pragma unroll
            for (int j = 0; j < 6; j++) {
                float w = wc[kk][cg * 6 + j];
                acc[j]      += xa.x * w;
                acc[6 + j]  += xa.y * w;
                acc[12 + j] += xb.x * w;
                acc[18 + j] += xb.y * w;
            }
        }
        __syncthreads();
    }

#pragma unroll
    for (int v = 0; v < 4; v++) {
        int n = n0 + ng * 4 + v;
        if (n < NN) {
#pragma unroll
            for (int j = 0; j < 6; j++) {
                int c = cg * 6 + j;
                float val = acc[v * 6 + j];
                if (c < 32) g_xs01[(size_t)n * 32 + c] = val;
                else        g_xroot[(size_t)n * 16 + (c - 32)] = val;
            }
        }
    }
}

// ---------------------------------------------------------------------------
// Pull pass 1 + node update: warp per dst node, no atomics.
__global__ __launch_bounds__(256) void pass1_kernel(const float* __restrict__ bias1) {
    int n = blockIdx.x * 8 + (threadIdx.x >> 5);
    if (n >= NN) return;
    int lane = threadIdx.x & 31;
    int f = lane & 15, half = lane >> 4;
    int beg = g_off[n];
    int deg = g_cnt[n];

    float acc = 0.f;
#pragma unroll 2
    for (int i = half; i < deg; i += 2) {
        float2 er = g_edges[beg + i];
        int s = __float_as_int(er.x);
        float u = er.y;
        const float* p = g_xs01 + (size_t)s * 32;
        acc += (1.f - u) * __ldg(p + f) + u * __ldg(p + 16 + f);
    }
    acc += __shfl_xor_sync(0xffffffffu, acc, 16);
    if (half == 0) {
        float v = acc * g_inv[n] + g_xroot[(size_t)n * 16 + f] + bias1[f];
        g_h[(size_t)n * 16 + f] = v > 0.f ? v : expm1f(v);
    }
}

// ---------------------------------------------------------------------------
// Pull pass 2 + final GEMM + log_softmax. Grid-stride warps; weights in regs.
__global__ __launch_bounds__(256) void pass2_final_kernel(
    const float* __restrict__ W2, const float* __restrict__ root2,
    const float* __restrict__ bias2, float* __restrict__ out) {
    const int lane = threadIdx.x & 31;
    const int f = lane & 15, half = lane >> 4;
    const int wid = blockIdx.x * 8 + (threadIdx.x >> 5);
    const int nwarps = gridDim.x * 8;

    float w0col[16], w1col[16], rcol[16];
#pragma unroll
    for (int k = 0; k < 16; k++) {
        w0col[k] = W2[k * NC + lane];
        w1col[k] = W2[16 * NC + k * NC + lane];
        rcol[k]  = root2[k * NC + lane];
    }
    const float bias = bias2[lane];

    for (int n = wid; n < NN; n += nwarps) {
        int beg = g_off[n];
        int deg = g_cnt[n];
        float a0 = 0.f, a1 = 0.f;
#pragma unroll 2
        for (int i = half; i < deg; i += 2) {
            float2 er = g_edges[beg + i];
            int s = __float_as_int(er.x);
            float u = er.y;
            float hv = __ldg(g_h + (size_t)s * 16 + f);
            a0 += (1.f - u) * hv;
            a1 += u * hv;
        }
        a0 += __shfl_xor_sync(0xffffffffu, a0, 16);
        a1 += __shfl_xor_sync(0xffffffffu, a1, 16);
        float hn = g_h[(size_t)n * 16 + f];

        float oagg = 0.f, oroot = 0.f;
#pragma unroll
        for (int k = 0; k < 16; k++) {
            float a0k = __shfl_sync(0xffffffffu, a0, k);
            float a1k = __shfl_sync(0xffffffffu, a1, k);
            float hk  = __shfl_sync(0xffffffffu, hn, k);
            oagg  += a0k * w0col[k] + a1k * w1col[k];
            oroot += hk * rcol[k];
        }
        float o = oagg * g_inv[n] + oroot + bias;

        float m = o;
#pragma unroll
        for (int off = 16; off; off >>= 1)
            m = fmaxf(m, __shfl_xor_sync(0xffffffffu, m, off));
        float ex = __expf(o - m);
        float ssum = ex;
#pragma unroll
        for (int off = 16; off; off >>= 1)
            ssum += __shfl_xor_sync(0xffffffffu, ssum, off);
        out[(size_t)n * 32 + lane] = o - m - logf(ssum);
    }
}

// ---------------------------------------------------------------------------
extern "C" void kernel_launch(void* const* d_in, const int* in_sizes, int n_in,
                              void* d_out, int out_size) {
    const float* x     = (const float*)d_in[0];
    const float* ea    = (const float*)d_in[1];
    const float* W1    = (const float*)d_in[2];
    const float* root1 = (const float*)d_in[3];
    const float* bias1 = (const float*)d_in[4];
    const float* W2    = (const float*)d_in[5];
    const float* root2 = (const float*)d_in[6];
    const float* bias2 = (const float*)d_in[7];
    const int*   ei    = (const int*)d_in[8];
    float* out = (float*)d_out;

    zero_kernel<<<(NN + 255) / 256, 256>>>();
    hist_kernel<<<(NE + 255) / 256, 256>>>(ei);
    scanA_kernel<<<NSCB, 256>>>();
    scanB_kernel<<<1, 32>>>();
    scanC_kernel<<<NSCB, 256>>>();
    scatter_kernel<<<(NE + 255) / 256, 256>>>(ei, ea);
    gemm1_kernel<<<(NN + 127) / 128, 256>>>(x, W1, root1);
    pass1_kernel<<<(NN + 7) / 8, 256>>>(bias1);
    pass2_final_kernel<<<1850, 256>>>(W2, root2, bias2, out);
}